// round 11
// baseline (speedup 1.0000x reference)
#include <cuda_runtime.h>
#include <cstddef>

typedef unsigned long long ULL;
typedef ulonglong2 UL2;

#define EPSF 1e-5f
#define HW 256
#define NSLICE 2048    // NB * HW
#define NODES 340      // 4 views * 5 T * 17 V
#define ST 20          // activation row stride (floats)
#define NG 3           // groups per CTA
#define GT 192         // threads per group
#define THREADS (NG*GT)

// ---- parameter table layout (floats) ----
#define CASP 0         // A_sp padded: 4*17 rows x 20  = 1360
#define CATM 1360      // A_tm padded: 2*5 rows x 8    = 80
#define CAVW 1440      // A_vw: 4x4                    = 16
#define CWG0 1456      // 7*18*16 [k][c][o], s1-folded = 2016
#define CWG1 3472      // 7*16*16                      = 1792
#define CWG2 5264      // 1792
#define CBG  7056      // 3*7*16, s1-folded            = 336
#define CB1  7392      // 336
#define CWT  7728      // 3*7*16*16 [l][k][c][o], s2-folded = 5376
#define CCI  13104     // 3*16: sum_k(bt*s2+b2)        = 48
#define CRSP 13152     // rowsum A_sp: 4 x 20          = 80
#define CRST 13232     // rowsum A_tm: 2 x 8           = 16
#define CRSV 13248     // rowsum A_vw: 4               = 4
#define CTOT 13252
#define CPAD 13264     // 16B-aligned pad

#define SMF  (CPAD + NG*2*NODES*ST)  // 13264 + 40800 = 54064 floats
#define SMB  (SMF*4)                 // 216256 B -> 1 CTA/SM, 18 warps

__device__ float gS[CPAD];

// group-local barrier (ids 1..NG), 192 threads each
#define GBAR(g) asm volatile("bar.sync %0, %1;" :: "r"((g) + 1), "r"(GT) : "memory")

// ---- packed-f32x2 helpers (Blackwell) ----
__device__ __forceinline__ ULL f2fma(ULL a, ULL b, ULL c){
  ULL d; asm("fma.rn.f32x2 %0,%1,%2,%3;" : "=l"(d) : "l"(a), "l"(b), "l"(c)); return d;
}
__device__ __forceinline__ ULL pkdup(float a){
  ULL d; asm("mov.b64 %0,{%1,%1};" : "=l"(d) : "f"(a), "f"(a)); return d;
}
__device__ __forceinline__ ULL pk(float a, float b){
  ULL d; asm("mov.b64 %0,{%1,%2};" : "=l"(d) : "f"(a), "f"(b)); return d;
}
__device__ __forceinline__ float2 up2(ULL a){
  float2 v; asm("mov.b64 {%0,%1},%2;" : "=f"(v.x), "=f"(v.y) : "l"(a)); return v;
}
__device__ __forceinline__ ULL lds2(const float* p){ return *reinterpret_cast<const ULL*>(p); }
__device__ __forceinline__ void sts2(float* p, ULL v){ *reinterpret_cast<ULL*>(p) = v; }
__device__ __forceinline__ float4 lds4(const float* p){ return *reinterpret_cast<const float4*>(p); }

// ---------------- prep ----------------
__global__ void prep_kernel(const float* __restrict__ A_sp, const float* __restrict__ A_tm,
                            const float* __restrict__ A_vw,
                            const float* __restrict__ Wg0, const float* __restrict__ bg0,
                            const float* __restrict__ Wg,  const float* __restrict__ bg,
                            const float* __restrict__ bn1g, const float* __restrict__ bn1b,
                            const float* __restrict__ Wt,  const float* __restrict__ bt,
                            const float* __restrict__ bn2g, const float* __restrict__ bn2b)
{
  const int t = threadIdx.x;
  const float inv = rsqrtf(1.f + EPSF);
  for (int i = t; i < 1360; i += 256){
    int k = i / 340, r = i % 340, u = r / 20, vp = r % 20;
    gS[CASP + i] = (vp < 17) ? A_sp[(k*17 + u)*17 + vp] : 0.f;
  }
  for (int i = t; i < 80; i += 256){
    int k = i / 40, r = i % 40, tt = r / 8, tp = r % 8;
    gS[CATM + i] = (tp < 5) ? A_tm[(k*5 + tt)*5 + tp] : 0.f;
  }
  for (int i = t; i < 16; i += 256) gS[CAVW + i] = A_vw[i];
  for (int i = t; i < 2016; i += 256){
    int k = i / 288, r = i % 288, o = r / 18, c = r % 18;
    gS[CWG0 + (k*18 + c)*16 + o] = Wg0[i] * (bn1g[k*16 + o] * inv);
  }
  for (int i = t; i < 3584; i += 256){
    int l = i / 1792, r = i % 1792, k = r / 256, q = r % 256, o = q / 16, c = q % 16;
    gS[CWG1 + l*1792 + (k*16 + c)*16 + o] = Wg[i] * (bn1g[((l+1)*7 + k)*16 + o] * inv);
  }
  for (int i = t; i < 336; i += 256){
    float bgv = (i < 112) ? bg0[i] : bg[i - 112];
    gS[CBG + i] = bgv * (bn1g[i] * inv);
    gS[CB1 + i] = bn1b[i];
  }
  for (int i = t; i < 5376; i += 256){
    int l = i / 1792, r = i % 1792, k = r / 256, q = r % 256, o = q / 16, c = q % 16;
    gS[CWT + l*1792 + (k*16 + c)*16 + o] = Wt[i] * (bn2g[(l*7 + k)*16 + o] * inv);
  }
  for (int i = t; i < 48; i += 256){
    int l = i / 16, o = i % 16;
    float s = 0.f;
    for (int k = 0; k < 7; k++){
      int id = (l*7 + k)*16 + o;
      s += bt[id] * (bn2g[id] * inv) + bn2b[id];
    }
    gS[CCI + i] = s;
  }
  for (int i = t; i < 80; i += 256){
    int k = i / 20, u = i % 20; float s = 0.f;
    if (u < 17) for (int j = 0; j < 17; j++) s += A_sp[(k*17 + u)*17 + j];
    gS[CRSP + i] = s;
  }
  for (int i = t; i < 16; i += 256){
    int k = i / 8, u = i % 8; float s = 0.f;
    if (u < 5) for (int j = 0; j < 5; j++) s += A_tm[(k*5 + u)*5 + j];
    gS[CRST + i] = s;
  }
  for (int i = t; i < 4; i += 256){
    float s = 0.f; for (int j = 0; j < 4; j++) s += A_vw[i*4 + j];
    gS[CRSV + i] = s;
  }
  for (int i = t; i < CPAD - CTOT; i += 256) gS[CTOT + i] = 0.f;
}

// ---- phase B: pure linear aggregation x -> z (sliced, per (node-group, ch-pair)) ----
template<int CP>
__device__ __forceinline__ void phBsp(const float* __restrict__ sP, const float* __restrict__ sX,
                                      float* __restrict__ sZ, int tid, int k)
{
  if (tid >= 20*CP) return;
  const int g = tid / CP, cp = tid - g*CP;
  const int base = g*17*ST + 2*cp;
  ULL ys[20];
  #pragma unroll
  for (int v = 0; v < 17; v++) ys[v] = lds2(sX + base + v*ST);
  ys[17] = 0ULL; ys[18] = 0ULL; ys[19] = 0ULL;
  const int ab = CASP + k*340;
  #pragma unroll
  for (int u = 0; u < 17; u++){
    ULL z = 0ULL;
    #pragma unroll
    for (int q = 0; q < 5; q++){
      float4 a = lds4(sP + ab + u*20 + 4*q);
      z = f2fma(ys[4*q + 0], pkdup(a.x), z);
      z = f2fma(ys[4*q + 1], pkdup(a.y), z);
      z = f2fma(ys[4*q + 2], pkdup(a.z), z);
      z = f2fma(ys[4*q + 3], pkdup(a.w), z);
    }
    sts2(sZ + base + u*ST, z);
  }
}

template<int CP>
__device__ __forceinline__ void phBtm(const float* __restrict__ sP, const float* __restrict__ sX,
                                      float* __restrict__ sZ, int tid, int k)
{
  const int ab = CATM + (k - 4)*40;
  for (int it = tid; it < 68*CP; it += GT){
    int vw = it / (17*CP); int r = it - vw*17*CP; int v = r / CP; int cp = r - v*CP;
    const int base = (vw*85 + v)*ST + 2*cp;
    ULL ys[5];
    #pragma unroll
    for (int tp = 0; tp < 5; tp++) ys[tp] = lds2(sX + base + tp*17*ST);
    #pragma unroll
    for (int t = 0; t < 5; t++){
      float4 a0 = lds4(sP + ab + t*8);
      float  a4 = sP[ab + t*8 + 4];
      ULL z = 0ULL;
      z = f2fma(ys[0], pkdup(a0.x), z);
      z = f2fma(ys[1], pkdup(a0.y), z);
      z = f2fma(ys[2], pkdup(a0.z), z);
      z = f2fma(ys[3], pkdup(a0.w), z);
      z = f2fma(ys[4], pkdup(a4),   z);
      sts2(sZ + base + t*17*ST, z);
    }
  }
}

template<int CP>
__device__ __forceinline__ void phBvw(const float* __restrict__ sP, const float* __restrict__ sX,
                                      float* __restrict__ sZ, int tid)
{
  for (int it = tid; it < 85*CP; it += GT){
    int t = it / (17*CP); int r = it - t*17*CP; int v = r / CP; int cp = r - v*CP;
    const int base = (t*17 + v)*ST + 2*cp;
    ULL ys[4];
    #pragma unroll
    for (int vw = 0; vw < 4; vw++) ys[vw] = lds2(sX + base + vw*85*ST);
    #pragma unroll
    for (int vo = 0; vo < 4; vo++){
      float4 a = lds4(sP + CAVW + vo*4);
      ULL z = 0ULL;
      z = f2fma(ys[0], pkdup(a.x), z);
      z = f2fma(ys[1], pkdup(a.y), z);
      z = f2fma(ys[2], pkdup(a.z), z);
      z = f2fma(ys[3], pkdup(a.w), z);
      sts2(sZ + base + vo*85*ST, z);
    }
  }
}

// ---- fused conv1 -> BN1(relu) -> conv2 -> acc, 2 nodes/thread ----
template<int CIN>
__device__ __forceinline__ void phaseAC(const float* __restrict__ sP, const float* __restrict__ sZ,
                                        int wb1, int wb2, int bgb, int b1b,
                                        float rs0, float rs1, int nd0, int nd1,
                                        ULL (&acc0)[8], ULL (&acc1)[8])
{
  constexpr int NQ = (CIN + 3) / 4;
  float z0[NQ*4], z1[NQ*4];
  #pragma unroll
  for (int q = 0; q < NQ; q++){
    float4 a = lds4(sZ + nd0*ST + 4*q);
    z0[4*q] = a.x; z0[4*q+1] = a.y; z0[4*q+2] = a.z; z0[4*q+3] = a.w;
    float4 b = lds4(sZ + nd1*ST + 4*q);
    z1[4*q] = b.x; z1[4*q+1] = b.y; z1[4*q+2] = b.z; z1[4*q+3] = b.w;
  }
  ULL y0[8], y1[8];
  {
    ULL rv0 = pkdup(rs0), rv1 = pkdup(rs1);
    #pragma unroll
    for (int q = 0; q < 4; q++){
      UL2 a = *reinterpret_cast<const UL2*>(sP + bgb + 4*q);
      UL2 b = *reinterpret_cast<const UL2*>(sP + b1b + 4*q);
      y0[2*q]   = f2fma(a.x, rv0, b.x);
      y0[2*q+1] = f2fma(a.y, rv0, b.y);
      y1[2*q]   = f2fma(a.x, rv1, b.x);
      y1[2*q+1] = f2fma(a.y, rv1, b.y);
    }
  }
  #pragma unroll
  for (int c = 0; c < CIN; c++){
    UL2 wA = *reinterpret_cast<const UL2*>(sP + wb1 + c*16);
    UL2 wB = *reinterpret_cast<const UL2*>(sP + wb1 + c*16 + 4);
    UL2 wC = *reinterpret_cast<const UL2*>(sP + wb1 + c*16 + 8);
    UL2 wD = *reinterpret_cast<const UL2*>(sP + wb1 + c*16 + 12);
    ULL xa = pkdup(z0[c]), xb = pkdup(z1[c]);
    y0[0] = f2fma(wA.x, xa, y0[0]); y1[0] = f2fma(wA.x, xb, y1[0]);
    y0[1] = f2fma(wA.y, xa, y0[1]); y1[1] = f2fma(wA.y, xb, y1[1]);
    y0[2] = f2fma(wB.x, xa, y0[2]); y1[2] = f2fma(wB.x, xb, y1[2]);
    y0[3] = f2fma(wB.y, xa, y0[3]); y1[3] = f2fma(wB.y, xb, y1[3]);
    y0[4] = f2fma(wC.x, xa, y0[4]); y1[4] = f2fma(wC.x, xb, y1[4]);
    y0[5] = f2fma(wC.y, xa, y0[5]); y1[5] = f2fma(wC.y, xb, y1[5]);
    y0[6] = f2fma(wD.x, xa, y0[6]); y1[6] = f2fma(wD.x, xb, y1[6]);
    y0[7] = f2fma(wD.y, xa, y0[7]); y1[7] = f2fma(wD.y, xb, y1[7]);
  }
  float r0[16], r1[16];
  #pragma unroll
  for (int q = 0; q < 8; q++){
    float2 f0 = up2(y0[q]);
    r0[2*q] = fmaxf(f0.x, 0.f); r0[2*q+1] = fmaxf(f0.y, 0.f);
    float2 f1 = up2(y1[q]);
    r1[2*q] = fmaxf(f1.x, 0.f); r1[2*q+1] = fmaxf(f1.y, 0.f);
  }
  #pragma unroll
  for (int c = 0; c < 16; c++){
    UL2 wA = *reinterpret_cast<const UL2*>(sP + wb2 + c*16);
    UL2 wB = *reinterpret_cast<const UL2*>(sP + wb2 + c*16 + 4);
    UL2 wC = *reinterpret_cast<const UL2*>(sP + wb2 + c*16 + 8);
    UL2 wD = *reinterpret_cast<const UL2*>(sP + wb2 + c*16 + 12);
    ULL xa = pkdup(r0[c]), xb = pkdup(r1[c]);
    acc0[0] = f2fma(wA.x, xa, acc0[0]); acc1[0] = f2fma(wA.x, xb, acc1[0]);
    acc0[1] = f2fma(wA.y, xa, acc0[1]); acc1[1] = f2fma(wA.y, xb, acc1[1]);
    acc0[2] = f2fma(wB.x, xa, acc0[2]); acc1[2] = f2fma(wB.x, xb, acc1[2]);
    acc0[3] = f2fma(wB.y, xa, acc0[3]); acc1[3] = f2fma(wB.y, xb, acc1[3]);
    acc0[4] = f2fma(wC.x, xa, acc0[4]); acc1[4] = f2fma(wC.x, xb, acc1[4]);
    acc0[5] = f2fma(wC.y, xa, acc0[5]); acc1[5] = f2fma(wC.y, xb, acc1[5]);
    acc0[6] = f2fma(wD.x, xa, acc0[6]); acc1[6] = f2fma(wD.x, xb, acc1[6]);
    acc0[7] = f2fma(wD.y, xa, acc0[7]); acc1[7] = f2fma(wD.y, xb, acc1[7]);
  }
}

// ---- one st_gcn layer (7 branches, aggregate-first), group-local barriers ----
template<int CIN>
__device__ __forceinline__ void run_layer(const float* __restrict__ sP,
    const float* __restrict__ sX, float* __restrict__ sZ,
    int gid, int gtid, int L, int wgb, bool act,
    int nd0, int nd1, int vv0, int vv1, int tc0, int tc1, int wc0, int wc1,
    ULL (&acc0)[8], ULL (&acc1)[8])
{
  constexpr int CP = CIN/2;
  #pragma unroll 1
  for (int k = 0; k < 7; k++){
    if (k < 4)      phBsp<CP>(sP, sX, sZ, gtid, k);
    else if (k < 6) phBtm<CP>(sP, sX, sZ, gtid, k);
    else            phBvw<CP>(sP, sX, sZ, gtid);
    GBAR(gid);
    if (act){
      float rs0, rs1;
      if (k < 4){ rs0 = sP[CRSP + k*20 + vv0]; rs1 = sP[CRSP + k*20 + vv1]; }
      else if (k < 6){ rs0 = sP[CRST + (k-4)*8 + tc0]; rs1 = sP[CRST + (k-4)*8 + tc1]; }
      else { rs0 = sP[CRSV + wc0]; rs1 = sP[CRSV + wc1]; }
      int wb1 = wgb + k*(CIN*16);
      int wb2 = CWT + (L*7 + k)*256;
      int bb  = (L*7 + k)*16;
      phaseAC<CIN>(sP, sZ, wb1, wb2, CBG + bb, CB1 + bb, rs0, rs1, nd0, nd1, acc0, acc1);
    }
    GBAR(gid);
  }
}

__device__ __forceinline__ void layer_boundary(const float* __restrict__ sP, float* __restrict__ sX,
                                               int Lnext, int nd0, int nd1,
                                               ULL (&acc0)[8], ULL (&acc1)[8])
{
  const int cib = CCI + Lnext*16;
  #pragma unroll
  for (int q = 0; q < 8; q++){
    float ci0 = sP[cib + 2*q], ci1 = sP[cib + 2*q + 1];
    float2 a = up2(acc0[q]);
    float x0 = fmaxf(a.x, 0.f), x1 = fmaxf(a.y, 0.f);
    sts2(sX + nd0*ST + 2*q, pk(x0, x1));
    acc0[q] = pk(fmaf(7.f, x0, ci0), fmaf(7.f, x1, ci1));
    float2 b = up2(acc1[q]);
    float u0 = fmaxf(b.x, 0.f), u1 = fmaxf(b.y, 0.f);
    sts2(sX + nd1*ST + 2*q, pk(u0, u1));
    acc1[q] = pk(fmaf(7.f, u0, ci0), fmaf(7.f, u1, ci1));
  }
}

// ---------------- fused 3-layer ST-GCN: 3 independent 192-thread groups per CTA ----------------
__global__ __launch_bounds__(THREADS, 1)
void stgcn_kernel(const float* __restrict__ x, float* __restrict__ out)
{
  extern __shared__ __align__(16) float smf[];
  float* sP = smf;

  const int tid  = threadIdx.x;
  const int gid  = tid / GT;
  const int gtid = tid - gid*GT;
  const int slice = blockIdx.x * NG + gid;

  // cooperative param load (all threads), one block-wide sync
  for (int i = tid*4; i < CPAD; i += THREADS*4)
    *reinterpret_cast<float4*>(sP + i) = *reinterpret_cast<const float4*>(gS + i);
  __syncthreads();

  if (slice >= NSLICE) return;
  const int n  = slice >> 8;     // / HW
  const int hw = slice & (HW-1);

  float* sX = smf + CPAD + gid*2*NODES*ST;
  float* sZ = sX + NODES*ST;

  {
    const float* xb = x + ((size_t)n * NODES * 18) * HW + hw;
    for (int i = gtid; i < NODES*18; i += GT){
      int ndd = i / 18, c = i - ndd*18;
      sX[ndd*ST + c] = xb[(size_t)i * HW];
    }
  }

  const bool act = gtid < 170;
  const int nd0 = gtid, nd1 = gtid + 170;
  const int vv0 = nd0 % 17, vv1 = nd1 % 17;
  const int tc0 = (nd0 / 17) % 5, tc1 = (nd1 / 17) % 5;
  const int wc0 = nd0 / 85, wc1 = nd1 / 85;

  ULL acc0[8], acc1[8];
  GBAR(gid);

  if (act){
    #pragma unroll
    for (int q = 0; q < 8; q++){
      ULL ci = lds2(sP + CCI + 2*q);
      acc0[q] = ci; acc1[q] = ci;
    }
  }

  run_layer<18>(sP, sX, sZ, gid, gtid, 0, CWG0, act, nd0, nd1, vv0, vv1, tc0, tc1, wc0, wc1, acc0, acc1);
  if (act) layer_boundary(sP, sX, 1, nd0, nd1, acc0, acc1);
  GBAR(gid);
  run_layer<16>(sP, sX, sZ, gid, gtid, 1, CWG1, act, nd0, nd1, vv0, vv1, tc0, tc1, wc0, wc1, acc0, acc1);
  if (act) layer_boundary(sP, sX, 2, nd0, nd1, acc0, acc1);
  GBAR(gid);
  run_layer<16>(sP, sX, sZ, gid, gtid, 2, CWG2, act, nd0, nd1, vv0, vv1, tc0, tc1, wc0, wc1, acc0, acc1);

  if (act){
    float* o0 = out + ((size_t)(n*NODES + nd0) * 16) * HW + hw;
    float* o1 = out + ((size_t)(n*NODES + nd1) * 16) * HW + hw;
    #pragma unroll
    for (int q = 0; q < 8; q++){
      float2 a = up2(acc0[q]);
      o0[(size_t)(2*q)     * HW] = fmaxf(a.x, 0.f);
      o0[(size_t)(2*q + 1) * HW] = fmaxf(a.y, 0.f);
      float2 b = up2(acc1[q]);
      o1[(size_t)(2*q)     * HW] = fmaxf(b.x, 0.f);
      o1[(size_t)(2*q + 1) * HW] = fmaxf(b.y, 0.f);
    }
  }
}

extern "C" void kernel_launch(void* const* d_in, const int* in_sizes, int n_in,
                              void* d_out, int out_size)
{
  (void)in_sizes; (void)n_in; (void)out_size;
  const float* x    = (const float*)d_in[0];
  const float* A_sp = (const float*)d_in[1];
  const float* A_tm = (const float*)d_in[2];
  const float* A_vw = (const float*)d_in[3];
  const float* Wg0  = (const float*)d_in[4];
  const float* bg0  = (const float*)d_in[5];
  const float* Wg   = (const float*)d_in[6];
  const float* bg   = (const float*)d_in[7];
  const float* bn1g = (const float*)d_in[8];
  const float* bn1b = (const float*)d_in[9];
  const float* Wt   = (const float*)d_in[10];
  const float* bt   = (const float*)d_in[11];
  const float* bn2g = (const float*)d_in[12];
  const float* bn2b = (const float*)d_in[13];

  cudaFuncSetAttribute(stgcn_kernel, cudaFuncAttributeMaxDynamicSharedMemorySize, SMB);

  prep_kernel<<<1, 256>>>(A_sp, A_tm, A_vw, Wg0, bg0, Wg, bg,
                          bn1g, bn1b, Wt, bt, bn2g, bn2b);
  const int nblk = (NSLICE + NG - 1) / NG;   // 683
  stgcn_kernel<<<nblk, THREADS, SMB>>>(x, (float*)d_out);
}

// round 12
// speedup vs baseline: 1.1118x; 1.1118x over previous
#include <cuda_runtime.h>
#include <cstddef>

typedef unsigned long long ULL;
typedef ulonglong2 UL2;

#define EPSF 1e-5f
#define NB 8
#define HW 256
#define NODES 340      // 4 views * 5 T * 17 V
#define PL 680         // plane stride in floats (340 nodes x float2)

// ---- parameter table layout (floats) ----
#define CASP 0         // A_sp padded: 4*17 rows x 20  = 1360
#define CATM 1360      // A_tm padded: 2*5 rows x 8    = 80
#define CAVW 1440      // A_vw: 4x4                    = 16
#define CWG0 1456      // 7*18*16 [k][c][o], s1-folded = 2016
#define CWG1 3472      // 7*16*16                      = 1792
#define CWG2 5264      // 1792
#define CBG  7056      // 3*7*16, s1-folded            = 336
#define CB1  7392      // 336
#define CWT  7728      // 3*7*16*16 [l][k][c][o], s2-folded = 5376
#define CCI  13104     // 3*16: sum_k(bt*s2+b2)        = 48
#define CTOT 13152     // 16B aligned

#define SACT CTOT                    // 9 planes x 680 floats
#define SMF  (SACT + 9*PL)           // 19272 floats
#define SMB  (SMF*4)                 // 77088 B -> 2 CTAs/SM

__device__ float gS[CTOT];

// ---- packed-f32x2 helpers (Blackwell) ----
__device__ __forceinline__ ULL f2fma(ULL a, ULL b, ULL c){
  ULL d; asm("fma.rn.f32x2 %0,%1,%2,%3;" : "=l"(d) : "l"(a), "l"(b), "l"(c)); return d;
}
__device__ __forceinline__ ULL f2add(ULL a, ULL b){
  ULL d; asm("add.rn.f32x2 %0,%1,%2;" : "=l"(d) : "l"(a), "l"(b)); return d;
}
__device__ __forceinline__ ULL pkdup(float a){
  ULL d; asm("mov.b64 %0,{%1,%1};" : "=l"(d) : "f"(a), "f"(a)); return d;
}
__device__ __forceinline__ ULL pk(float a, float b){
  ULL d; asm("mov.b64 %0,{%1,%2};" : "=l"(d) : "f"(a), "f"(b)); return d;
}
__device__ __forceinline__ float2 up2(ULL a){
  float2 v; asm("mov.b64 {%0,%1},%2;" : "=f"(v.x), "=f"(v.y) : "l"(a)); return v;
}
__device__ __forceinline__ ULL lds2(const float* p){ return *reinterpret_cast<const ULL*>(p); }
__device__ __forceinline__ void sts2(float* p, ULL v){ *reinterpret_cast<ULL*>(p) = v; }
__device__ __forceinline__ float4 lds4(const float* p){ return *reinterpret_cast<const float4*>(p); }

// ---------------- prep: fold BN scales into weights, pad A, transpose ----------------
__global__ void prep_kernel(const float* __restrict__ A_sp, const float* __restrict__ A_tm,
                            const float* __restrict__ A_vw,
                            const float* __restrict__ Wg0, const float* __restrict__ bg0,
                            const float* __restrict__ Wg,  const float* __restrict__ bg,
                            const float* __restrict__ bn1g, const float* __restrict__ bn1b,
                            const float* __restrict__ Wt,  const float* __restrict__ bt,
                            const float* __restrict__ bn2g, const float* __restrict__ bn2b)
{
  const int t = threadIdx.x;
  const float inv = rsqrtf(1.f + EPSF);
  for (int i = t; i < 1360; i += 256){
    int k = i / 340, r = i % 340, u = r / 20, vp = r % 20;
    gS[CASP + i] = (vp < 17) ? A_sp[(k*17 + u)*17 + vp] : 0.f;
  }
  for (int i = t; i < 80; i += 256){
    int k = i / 40, r = i % 40, tt = r / 8, tp = r % 8;
    gS[CATM + i] = (tp < 5) ? A_tm[(k*5 + tt)*5 + tp] : 0.f;
  }
  for (int i = t; i < 16; i += 256) gS[CAVW + i] = A_vw[i];
  for (int i = t; i < 2016; i += 256){
    int k = i / 288, r = i % 288, o = r / 18, c = r % 18;
    gS[CWG0 + (k*18 + c)*16 + o] = Wg0[i] * (bn1g[k*16 + o] * inv);
  }
  for (int i = t; i < 3584; i += 256){
    int l = i / 1792, r = i % 1792, k = r / 256, q = r % 256, o = q / 16, c = q % 16;
    gS[CWG1 + l*1792 + (k*16 + c)*16 + o] = Wg[i] * (bn1g[((l+1)*7 + k)*16 + o] * inv);
  }
  for (int i = t; i < 336; i += 256){
    float bgv = (i < 112) ? bg0[i] : bg[i - 112];
    gS[CBG + i] = bgv * (bn1g[i] * inv);
    gS[CB1 + i] = bn1b[i];
  }
  for (int i = t; i < 5376; i += 256){
    int l = i / 1792, r = i % 1792, k = r / 256, q = r % 256, o = q / 16, c = q % 16;
    gS[CWT + l*1792 + (k*16 + c)*16 + o] = Wt[i] * (bn2g[(l*7 + k)*16 + o] * inv);
  }
  for (int i = t; i < 48; i += 256){
    int l = i / 16, o = i % 16;
    float s = 0.f;
    for (int k = 0; k < 7; k++){
      int id = (l*7 + k)*16 + o;
      s += bt[id] * (bn2g[id] * inv) + bn2b[id];
    }
    gS[CCI + i] = s;
  }
}

// ---- phase A: conv1 (s1-folded) from register-stationary x -> y planes ----
template<int CIN>
__device__ __forceinline__ void phaseA(const float* __restrict__ sP, float* __restrict__ sY,
                                       int wb, int bb,
                                       const float (&xr0)[18], const float (&xr1)[18],
                                       int nd0, int nd1)
{
  ULL y0[8], y1[8];
  #pragma unroll
  for (int q = 0; q < 4; q++){
    UL2 b = *reinterpret_cast<const UL2*>(sP + bb + 4*q);
    y0[2*q] = b.x; y0[2*q+1] = b.y;
    y1[2*q] = b.x; y1[2*q+1] = b.y;
  }
  #pragma unroll
  for (int c = 0; c < CIN; c++){
    UL2 wA = *reinterpret_cast<const UL2*>(sP + wb + c*16);
    UL2 wB = *reinterpret_cast<const UL2*>(sP + wb + c*16 + 4);
    UL2 wC = *reinterpret_cast<const UL2*>(sP + wb + c*16 + 8);
    UL2 wD = *reinterpret_cast<const UL2*>(sP + wb + c*16 + 12);
    ULL xa = pkdup(xr0[c]), xb = pkdup(xr1[c]);
    y0[0] = f2fma(wA.x, xa, y0[0]); y1[0] = f2fma(wA.x, xb, y1[0]);
    y0[1] = f2fma(wA.y, xa, y0[1]); y1[1] = f2fma(wA.y, xb, y1[1]);
    y0[2] = f2fma(wB.x, xa, y0[2]); y1[2] = f2fma(wB.x, xb, y1[2]);
    y0[3] = f2fma(wB.y, xa, y0[3]); y1[3] = f2fma(wB.y, xb, y1[3]);
    y0[4] = f2fma(wC.x, xa, y0[4]); y1[4] = f2fma(wC.x, xb, y1[4]);
    y0[5] = f2fma(wC.y, xa, y0[5]); y1[5] = f2fma(wC.y, xb, y1[5]);
    y0[6] = f2fma(wD.x, xa, y0[6]); y1[6] = f2fma(wD.x, xb, y1[6]);
    y0[7] = f2fma(wD.y, xa, y0[7]); y1[7] = f2fma(wD.y, xb, y1[7]);
  }
  #pragma unroll
  for (int p = 0; p < 8; p++){
    sts2(sY + p*PL + nd0*2, y0[p]);
    sts2(sY + p*PL + nd1*2, y1[p]);
  }
}

// ---- phase C: conv2 (s2-folded) reading own aggregated rows (planes) ----
__device__ __forceinline__ void phaseC(const float* __restrict__ sP, const float* __restrict__ sY,
                                       int wb, int nd0, int nd1,
                                       ULL (&acc0)[8], ULL (&acc1)[8])
{
  float r0[16], r1[16];
  #pragma unroll
  for (int p = 0; p < 8; p++){
    float2 a = up2(lds2(sY + p*PL + nd0*2));
    r0[2*p] = a.x; r0[2*p+1] = a.y;
    float2 b = up2(lds2(sY + p*PL + nd1*2));
    r1[2*p] = b.x; r1[2*p+1] = b.y;
  }
  #pragma unroll
  for (int c = 0; c < 16; c++){
    UL2 wA = *reinterpret_cast<const UL2*>(sP + wb + c*16);
    UL2 wB = *reinterpret_cast<const UL2*>(sP + wb + c*16 + 4);
    UL2 wC = *reinterpret_cast<const UL2*>(sP + wb + c*16 + 8);
    UL2 wD = *reinterpret_cast<const UL2*>(sP + wb + c*16 + 12);
    ULL xa = pkdup(r0[c]), xb = pkdup(r1[c]);
    acc0[0] = f2fma(wA.x, xa, acc0[0]); acc1[0] = f2fma(wA.x, xb, acc1[0]);
    acc0[1] = f2fma(wA.y, xa, acc0[1]); acc1[1] = f2fma(wA.y, xb, acc1[1]);
    acc0[2] = f2fma(wB.x, xa, acc0[2]); acc1[2] = f2fma(wB.x, xb, acc1[2]);
    acc0[3] = f2fma(wB.y, xa, acc0[3]); acc1[3] = f2fma(wB.y, xb, acc1[3]);
    acc0[4] = f2fma(wC.x, xa, acc0[4]); acc1[4] = f2fma(wC.x, xb, acc1[4]);
    acc0[5] = f2fma(wC.y, xa, acc0[5]); acc1[5] = f2fma(wC.y, xb, acc1[5]);
    acc0[6] = f2fma(wD.x, xa, acc0[6]); acc1[6] = f2fma(wD.x, xb, acc1[6]);
    acc0[7] = f2fma(wD.y, xa, acc0[7]); acc1[7] = f2fma(wD.y, xb, acc1[7]);
  }
}

// ---- phase B spatial: in-place agg on y planes + b1 + ReLU. thread = (cp, g) ----
__device__ __forceinline__ void phaseBsp(const float* __restrict__ sP, float* __restrict__ sY,
                                         int tid, int L, int k)
{
  if (tid >= 160) return;
  const int cp = tid / 20, g = tid - cp*20;
  float* base = sY + cp*PL + g*17*2;
  ULL ys[20];
  #pragma unroll
  for (int v = 0; v < 17; v++) ys[v] = lds2(base + v*2);
  ys[17] = 0ULL; ys[18] = 0ULL; ys[19] = 0ULL;
  const ULL b1 = lds2(sP + CB1 + (L*7 + k)*16 + 2*cp);
  const int ab = CASP + k*340;
  #pragma unroll
  for (int u = 0; u < 17; u++){
    ULL z = 0ULL;
    #pragma unroll
    for (int q = 0; q < 5; q++){
      float4 a = lds4(sP + ab + u*20 + 4*q);
      z = f2fma(ys[4*q + 0], pkdup(a.x), z);
      z = f2fma(ys[4*q + 1], pkdup(a.y), z);
      z = f2fma(ys[4*q + 2], pkdup(a.z), z);
      z = f2fma(ys[4*q + 3], pkdup(a.w), z);
    }
    float2 f = up2(f2add(z, b1));
    sts2(base + u*2, pk(fmaxf(f.x, 0.f), fmaxf(f.y, 0.f)));
  }
}

// ---- phase B temporal: thread slot = (cp, vw, v) ----
__device__ __forceinline__ void phaseBtm(const float* __restrict__ sP, float* __restrict__ sY,
                                         int tid, int L, int k)
{
  const int b1b = CB1 + (L*7 + k)*16;
  const int ab  = CATM + (k - 4)*40;
  for (int it = tid; it < 544; it += 192){
    int cp = it / 68; int r = it - cp*68; int vw = r / 17; int v = r - vw*17;
    float* base = sY + cp*PL + (vw*85 + v)*2;
    ULL ys[5];
    #pragma unroll
    for (int tp = 0; tp < 5; tp++) ys[tp] = lds2(base + tp*34);
    const ULL b1 = lds2(sP + b1b + 2*cp);
    #pragma unroll
    for (int t = 0; t < 5; t++){
      float4 a0 = lds4(sP + ab + t*8);
      float  a4 = sP[ab + t*8 + 4];
      ULL z = 0ULL;
      z = f2fma(ys[0], pkdup(a0.x), z);
      z = f2fma(ys[1], pkdup(a0.y), z);
      z = f2fma(ys[2], pkdup(a0.z), z);
      z = f2fma(ys[3], pkdup(a0.w), z);
      z = f2fma(ys[4], pkdup(a4),   z);
      float2 f = up2(f2add(z, b1));
      sts2(base + t*34, pk(fmaxf(f.x, 0.f), fmaxf(f.y, 0.f)));
    }
  }
}

// ---- phase B views: thread slot = (cp, t, v) ----
__device__ __forceinline__ void phaseBvw(const float* __restrict__ sP, float* __restrict__ sY,
                                         int tid, int L)
{
  const int b1b = CB1 + (L*7 + 6)*16;
  for (int it = tid; it < 680; it += 192){
    int cp = it / 85; int r = it - cp*85; int t = r / 17; int v = r - t*17;
    float* base = sY + cp*PL + (t*17 + v)*2;
    ULL ys[4];
    #pragma unroll
    for (int vw = 0; vw < 4; vw++) ys[vw] = lds2(base + vw*170);
    const ULL b1 = lds2(sP + b1b + 2*cp);
    #pragma unroll
    for (int vo = 0; vo < 4; vo++){
      float4 a = lds4(sP + CAVW + vo*4);
      ULL z = 0ULL;
      z = f2fma(ys[0], pkdup(a.x), z);
      z = f2fma(ys[1], pkdup(a.y), z);
      z = f2fma(ys[2], pkdup(a.z), z);
      z = f2fma(ys[3], pkdup(a.w), z);
      float2 f = up2(f2add(z, b1));
      sts2(base + vo*170, pk(fmaxf(f.x, 0.f), fmaxf(f.y, 0.f)));
    }
  }
}

// ---------------- fused 3-layer ST-GCN: one CTA per (n, hw) ----------------
__global__ __launch_bounds__(192, 2)
void stgcn_kernel(const float* __restrict__ x, float* __restrict__ out)
{
  extern __shared__ __align__(16) float smf[];
  float* sP = smf;
  float* sY = smf + SACT;

  const int hw  = blockIdx.x;
  const int n   = blockIdx.y;
  const int tid = threadIdx.x;

  for (int i = tid*4; i < CTOT; i += 192*4)
    *reinterpret_cast<float4*>(sP + i) = *reinterpret_cast<const float4*>(gS + i);
  // load x into 9 channel-pair planes
  {
    const float* xb = x + ((size_t)n * NODES * 18) * HW + hw;
    for (int i = tid; i < NODES*9; i += 192){
      int cp = i / NODES, node = i - cp*NODES;
      float v0 = xb[(size_t)(node*18 + 2*cp)     * HW];
      float v1 = xb[(size_t)(node*18 + 2*cp + 1) * HW];
      sts2(sY + cp*PL + node*2, pk(v0, v1));
    }
  }
  __syncthreads();

  const bool act = tid < 170;
  const int nd0 = tid, nd1 = tid + 170;

  ULL acc0[8], acc1[8];
  float xr0[18], xr1[18];

  if (act){
    #pragma unroll
    for (int cp = 0; cp < 9; cp++){
      float2 a = up2(lds2(sY + cp*PL + nd0*2));
      xr0[2*cp] = a.x; xr0[2*cp+1] = a.y;
      float2 b = up2(lds2(sY + cp*PL + nd1*2));
      xr1[2*cp] = b.x; xr1[2*cp+1] = b.y;
    }
    #pragma unroll
    for (int q = 0; q < 8; q++){
      ULL ci = lds2(sP + CCI + 2*q);
      acc0[q] = ci; acc1[q] = ci;
    }
  }
  __syncthreads();           // x reads done before y overwrites planes
  if (act) phaseA<18>(sP, sY, CWG0, CBG, xr0, xr1, nd0, nd1);
  __syncthreads();

  #pragma unroll 1
  for (int L = 0; L < 3; L++){
    const int wgb = (L == 0) ? CWG0 : (L == 1 ? CWG1 : CWG2);
    const int cinw = (L == 0) ? 288 : 256;
    #pragma unroll 1
    for (int k = 0; k < 7; k++){
      if (k < 4)      phaseBsp(sP, sY, tid, L, k);
      else if (k < 6) phaseBtm(sP, sY, tid, L, k);
      else            phaseBvw(sP, sY, tid, L);
      __syncthreads();
      if (act){
        phaseC(sP, sY, CWT + (L*7 + k)*256, nd0, nd1, acc0, acc1);
        if (k < 6){
          int wb = wgb + (k+1)*cinw;
          int bb = CBG + (L*7 + k + 1)*16;
          if (L == 0) phaseA<18>(sP, sY, wb, bb, xr0, xr1, nd0, nd1);
          else        phaseA<16>(sP, sY, wb, bb, xr0, xr1, nd0, nd1);
        } else if (L < 2){
          // layer boundary: xr = relu(acc); acc = CI(next) + 7*xr
          const int cib = CCI + (L+1)*16;
          #pragma unroll
          for (int q = 0; q < 8; q++){
            float ci0 = sP[cib + 2*q], ci1 = sP[cib + 2*q + 1];
            float2 a = up2(acc0[q]);
            float x0 = fmaxf(a.x, 0.f), x1 = fmaxf(a.y, 0.f);
            xr0[2*q] = x0; xr0[2*q+1] = x1;
            acc0[q] = pk(fmaf(7.f, x0, ci0), fmaf(7.f, x1, ci1));
            float2 b = up2(acc1[q]);
            float u0 = fmaxf(b.x, 0.f), u1 = fmaxf(b.y, 0.f);
            xr1[2*q] = u0; xr1[2*q+1] = u1;
            acc1[q] = pk(fmaf(7.f, u0, ci0), fmaf(7.f, u1, ci1));
          }
          int wb = (L == 0) ? CWG1 : CWG2;
          int bb = CBG + (L+1)*7*16;
          phaseA<16>(sP, sY, wb, bb, xr0, xr1, nd0, nd1);
        }
      }
      __syncthreads();
    }
  }

  // ---- final ReLU + output ----
  if (act){
    float* o0 = out + ((size_t)(n*NODES + nd0) * 16) * HW + hw;
    float* o1 = out + ((size_t)(n*NODES + nd1) * 16) * HW + hw;
    #pragma unroll
    for (int q = 0; q < 8; q++){
      float2 a = up2(acc0[q]);
      o0[(size_t)(2*q)     * HW] = fmaxf(a.x, 0.f);
      o0[(size_t)(2*q + 1) * HW] = fmaxf(a.y, 0.f);
      float2 b = up2(acc1[q]);
      o1[(size_t)(2*q)     * HW] = fmaxf(b.x, 0.f);
      o1[(size_t)(2*q + 1) * HW] = fmaxf(b.y, 0.f);
    }
  }
}

extern "C" void kernel_launch(void* const* d_in, const int* in_sizes, int n_in,
                              void* d_out, int out_size)
{
  (void)in_sizes; (void)n_in; (void)out_size;
  const float* x    = (const float*)d_in[0];
  const float* A_sp = (const float*)d_in[1];
  const float* A_tm = (const float*)d_in[2];
  const float* A_vw = (const float*)d_in[3];
  const float* Wg0  = (const float*)d_in[4];
  const float* bg0  = (const float*)d_in[5];
  const float* Wg   = (const float*)d_in[6];
  const float* bg   = (const float*)d_in[7];
  const float* bn1g = (const float*)d_in[8];
  const float* bn1b = (const float*)d_in[9];
  const float* Wt   = (const float*)d_in[10];
  const float* bt   = (const float*)d_in[11];
  const float* bn2g = (const float*)d_in[12];
  const float* bn2b = (const float*)d_in[13];

  cudaFuncSetAttribute(stgcn_kernel, cudaFuncAttributeMaxDynamicSharedMemorySize, SMB);

  prep_kernel<<<1, 256>>>(A_sp, A_tm, A_vw, Wg0, bg0, Wg, bg,
                          bn1g, bn1b, Wt, bt, bn2g, bn2b);
  stgcn_kernel<<<dim3(HW, NB), 192, SMB>>>(x, (float*)d_out);
}